// round 1
// baseline (speedup 1.0000x reference)
#include <cuda_runtime.h>
#include <math.h>

#define NN 4096
#define EE 131072
#define FF 64
#define HIDD 64
#define OUTD 86
#define BB 16
#define NHEADS 4
#define DH 16

// ------------------------- scratch (device globals; no allocs) -------------
__device__ float g_deg[NN];
__device__ float g_dis[NN];
__device__ float g_hw[NN * HIDD];     // x @ W1^T
__device__ float g_agg1[NN * HIDD];   // scatter target GCN1
__device__ float g_h[NN * HIDD];      // relu(agg + selfloop + b1)
__device__ float g_qkv[NN * 3 * HIDD];
__device__ float g_o[NN * HIDD];      // attention output (pre out-proj)
__device__ float g_ow[NN * HIDD];     // o @ Wout^T + b_out
__device__ float g_h2w[NN * OUTD];    // ow @ W2^T
__device__ float g_agg2[NN * OUTD];   // scatter target GCN2
__device__ float g_pool[BB * OUTD];
__device__ float g_cnt[BB];

// ------------------------- init / degree / norm ----------------------------
__global__ void init_kernel() {
    int idx = blockIdx.x * blockDim.x + threadIdx.x;
    if (idx < NN * HIDD) g_agg1[idx] = 0.0f;
    if (idx < NN * OUTD) g_agg2[idx] = 0.0f;
    if (idx < BB * OUTD) g_pool[idx] = 0.0f;
    if (idx < BB) g_cnt[idx] = 0.0f;
    if (idx < NN) g_deg[idx] = 1.0f;   // self-loop weight 1
}

__global__ void deg_kernel(const int* __restrict__ ei, const float* __restrict__ ea) {
    int e = blockIdx.x * blockDim.x + threadIdx.x;
    if (e < EE) {
        int d = ei[EE + e];
        atomicAdd(&g_deg[d], ea[e]);
    }
}

__global__ void dis_kernel() {
    int i = blockIdx.x * blockDim.x + threadIdx.x;
    if (i < NN) g_dis[i] = rsqrtf(g_deg[i]);   // deg >= 1 always (self loops)
}

// ------------------------- generic small GEMM out = in @ W^T (+bias) -------
// in: [nrows, 64], W: [KOUT, 64] row-major, out: [nrows, KOUT]
template <int KOUT, bool BIAS>
__global__ void gemm64(const float* __restrict__ in, const float* __restrict__ W,
                       const float* __restrict__ bias, float* __restrict__ out) {
    constexpr int KP  = ((KOUT + 31) / 32) * 32;  // padded col count (mult of 32)
    constexpr int KPP = KP + 1;                    // smem row stride (odd -> no conflicts)
    constexpr int CT  = KP / 32;                   // cols per thread
    constexpr int RT  = 4;                         // rows per thread
    constexpr int ROWS = 32;                       // rows per block (8 ty * RT)
    extern __shared__ float sm[];
    float* Wsh = sm;                 // [64][KPP]  (k-major)
    float* xsh = sm + 64 * KPP;      // [ROWS][65]
    int tid = threadIdx.x;           // 256 threads

    // W[c][k] -> Wsh[k][c], zero-pad c in [KOUT, KP)
    for (int idx = tid; idx < 64 * KP; idx += 256) {
        int k = idx & 63;
        int c = idx >> 6;
        float w = (c < KOUT) ? W[c * 64 + k] : 0.0f;
        Wsh[k * KPP + c] = w;
    }
    int row0 = blockIdx.x * ROWS;
    for (int idx = tid; idx < ROWS * 64; idx += 256) {
        int r = idx >> 6, k = idx & 63;
        xsh[r * 65 + k] = in[(row0 + r) * 64 + k];
    }
    __syncthreads();

    int tx = tid & 31, ty = tid >> 5;   // ty 0..7
    float acc[RT][CT];
#pragma unroll
    for (int i = 0; i < RT; i++)
#pragma unroll
        for (int j = 0; j < CT; j++) acc[i][j] = 0.0f;

#pragma unroll 4
    for (int k = 0; k < 64; k++) {
        float xv[RT];
#pragma unroll
        for (int i = 0; i < RT; i++) xv[i] = xsh[(ty * RT + i) * 65 + k];
#pragma unroll
        for (int j = 0; j < CT; j++) {
            float wv = Wsh[k * KPP + tx + j * 32];
#pragma unroll
            for (int i = 0; i < RT; i++) acc[i][j] = fmaf(xv[i], wv, acc[i][j]);
        }
    }
#pragma unroll
    for (int i = 0; i < RT; i++) {
        int r = row0 + ty * RT + i;
#pragma unroll
        for (int j = 0; j < CT; j++) {
            int c = tx + j * 32;
            if (c < KOUT) {
                float v = acc[i][j];
                if (BIAS) v += bias[c];
                out[r * KOUT + c] = v;
            }
        }
    }
}

// ------------------------- GCN scatter (warp per edge) ---------------------
__global__ void scatter64_kernel(const int* __restrict__ ei, const float* __restrict__ ea) {
    int w = (blockIdx.x * blockDim.x + threadIdx.x) >> 5;
    int lane = threadIdx.x & 31;
    if (w >= EE) return;
    int s = ei[w];
    int d = ei[EE + w];
    float coef = g_dis[s] * ea[w] * g_dis[d];
    float v0 = g_hw[s * 64 + lane];
    float v1 = g_hw[s * 64 + 32 + lane];
    atomicAdd(&g_agg1[d * 64 + lane], coef * v0);
    atomicAdd(&g_agg1[d * 64 + 32 + lane], coef * v1);
}

__global__ void post1_kernel(const float* __restrict__ b1) {
    int idx = blockIdx.x * blockDim.x + threadIdx.x;
    if (idx >= NN * HIDD) return;
    int i = idx >> 6, f = idx & 63;
    float di = g_dis[i];
    float v = g_agg1[idx] + di * di * g_hw[idx] + b1[f];
    g_h[idx] = fmaxf(v, 0.0f);
}

// ------------------------- flash attention (4 heads, dh=16) ----------------
// grid (NN/128, NHEADS), block 128. Thread-per-query, K/V tiles of 64 in smem.
__global__ void attn_kernel() {
    int head = blockIdx.y;
    int q = blockIdx.x * 128 + threadIdx.x;
    __shared__ float4 Ksh[64][4];
    __shared__ float4 Vsh[64][4];

    const float* qp = g_qkv + q * 192 + head * DH;
    const float SC = 0.25f * 1.44269504088896f;   // 1/sqrt(dh) * log2(e)
    float qr[16];
#pragma unroll
    for (int d = 0; d < 16; d++) qr[d] = qp[d] * SC;

    float m = -1e30f, l = 0.0f;
    float acc[16];
#pragma unroll
    for (int d = 0; d < 16; d++) acc[d] = 0.0f;

    for (int t = 0; t < NN / 64; t++) {
        __syncthreads();
        for (int i = threadIdx.x; i < 256; i += 128) {
            int j = i >> 2, d4 = i & 3;
            const float* base = g_qkv + (t * 64 + j) * 192 + head * DH + d4 * 4;
            Ksh[j][d4] = *(const float4*)(base + 64);
            Vsh[j][d4] = *(const float4*)(base + 128);
        }
        __syncthreads();
#pragma unroll 2
        for (int j = 0; j < 64; j++) {
            float4 k0 = Ksh[j][0], k1 = Ksh[j][1], k2 = Ksh[j][2], k3 = Ksh[j][3];
            float s0 = qr[0] * k0.x;  s0 = fmaf(qr[1], k0.y, s0);
            s0 = fmaf(qr[2], k0.z, s0);  s0 = fmaf(qr[3], k0.w, s0);
            float s1 = qr[4] * k1.x;  s1 = fmaf(qr[5], k1.y, s1);
            s1 = fmaf(qr[6], k1.z, s1);  s1 = fmaf(qr[7], k1.w, s1);
            float s2 = qr[8] * k2.x;  s2 = fmaf(qr[9], k2.y, s2);
            s2 = fmaf(qr[10], k2.z, s2); s2 = fmaf(qr[11], k2.w, s2);
            float s3 = qr[12] * k3.x; s3 = fmaf(qr[13], k3.y, s3);
            s3 = fmaf(qr[14], k3.z, s3); s3 = fmaf(qr[15], k3.w, s3);
            float s = (s0 + s1) + (s2 + s3);

            float p;
            if (s > m) {
                float sc = exp2f(m - s);
                m = s;
                l *= sc;
#pragma unroll
                for (int d = 0; d < 16; d++) acc[d] *= sc;
                p = 1.0f;
            } else {
                p = exp2f(s - m);
            }
            l += p;
            float4 v0 = Vsh[j][0], v1 = Vsh[j][1], v2 = Vsh[j][2], v3 = Vsh[j][3];
            acc[0]  = fmaf(p, v0.x, acc[0]);  acc[1]  = fmaf(p, v0.y, acc[1]);
            acc[2]  = fmaf(p, v0.z, acc[2]);  acc[3]  = fmaf(p, v0.w, acc[3]);
            acc[4]  = fmaf(p, v1.x, acc[4]);  acc[5]  = fmaf(p, v1.y, acc[5]);
            acc[6]  = fmaf(p, v1.z, acc[6]);  acc[7]  = fmaf(p, v1.w, acc[7]);
            acc[8]  = fmaf(p, v2.x, acc[8]);  acc[9]  = fmaf(p, v2.y, acc[9]);
            acc[10] = fmaf(p, v2.z, acc[10]); acc[11] = fmaf(p, v2.w, acc[11]);
            acc[12] = fmaf(p, v3.x, acc[12]); acc[13] = fmaf(p, v3.y, acc[13]);
            acc[14] = fmaf(p, v3.z, acc[14]); acc[15] = fmaf(p, v3.w, acc[15]);
        }
    }
    float inv = 1.0f / l;
    float* op = g_o + q * 64 + head * DH;
#pragma unroll
    for (int d = 0; d < 16; d++) op[d] = acc[d] * inv;
}

// ------------------------- GCN2 scatter (86 features) -----------------------
__global__ void scatter86_kernel(const int* __restrict__ ei, const float* __restrict__ ea) {
    int w = (blockIdx.x * blockDim.x + threadIdx.x) >> 5;
    int lane = threadIdx.x & 31;
    if (w >= EE) return;
    int s = ei[w];
    int d = ei[EE + w];
    float coef = g_dis[s] * ea[w] * g_dis[d];
    for (int f = lane; f < OUTD; f += 32) {
        atomicAdd(&g_agg2[d * OUTD + f], coef * g_h2w[s * OUTD + f]);
    }
}

__global__ void cnt_kernel(const int* __restrict__ batch) {
    int i = blockIdx.x * blockDim.x + threadIdx.x;
    if (i < NN) atomicAdd(&g_cnt[batch[i]], 1.0f);
}

__global__ void final_node_kernel(const int* __restrict__ batch, const float* __restrict__ b2) {
    int idx = blockIdx.x * blockDim.x + threadIdx.x;
    if (idx >= NN * OUTD) return;
    int i = idx / OUTD, f = idx - i * OUTD;
    float di = g_dis[i];
    float v = g_agg2[idx] + di * di * g_h2w[idx] + b2[f];
    atomicAdd(&g_pool[batch[i] * OUTD + f], v);
}

__global__ void out_kernel(float* __restrict__ out) {
    int idx = blockIdx.x * blockDim.x + threadIdx.x;
    if (idx >= BB * OUTD) return;
    int b = idx / OUTD;
    out[idx] = g_pool[idx] / fmaxf(g_cnt[b], 1.0f);
}

// ------------------------- launch ------------------------------------------
extern "C" void kernel_launch(void* const* d_in, const int* in_sizes, int n_in,
                              void* d_out, int out_size) {
    const float* x     = (const float*)d_in[0];
    const int*   ei    = (const int*)  d_in[1];
    const float* ea    = (const float*)d_in[2];
    const int*   batch = (const int*)  d_in[3];
    const float* W1    = (const float*)d_in[4];
    const float* b1    = (const float*)d_in[5];
    const float* Win   = (const float*)d_in[6];
    const float* b_in  = (const float*)d_in[7];
    const float* Wout  = (const float*)d_in[8];
    const float* b_out = (const float*)d_in[9];
    const float* W2    = (const float*)d_in[10];
    const float* b2    = (const float*)d_in[11];
    float* out = (float*)d_out;

    float *p_hw, *p_h, *p_qkv, *p_o, *p_ow, *p_h2w;
    cudaGetSymbolAddress((void**)&p_hw,  g_hw);
    cudaGetSymbolAddress((void**)&p_h,   g_h);
    cudaGetSymbolAddress((void**)&p_qkv, g_qkv);
    cudaGetSymbolAddress((void**)&p_o,   g_o);
    cudaGetSymbolAddress((void**)&p_ow,  g_ow);
    cudaGetSymbolAddress((void**)&p_h2w, g_h2w);

    // dynamic smem sizes for gemm64 variants
    const int sm64  = (64 * 65  + 32 * 65) * 4;   // 24960 B
    const int sm86  = (64 * 97  + 32 * 65) * 4;   // 33152 B
    const int sm192 = (64 * 193 + 32 * 65) * 4;   // 57728 B
    cudaFuncSetAttribute(gemm64<192, true>, cudaFuncAttributeMaxDynamicSharedMemorySize, sm192);

    // 1. zero / init
    init_kernel<<<(NN * OUTD + 255) / 256, 256>>>();
    // 2. degree accumulation + normalization factors
    deg_kernel<<<EE / 256, 256>>>(ei, ea);
    dis_kernel<<<NN / 256, 256>>>();
    // 3. GCN1 linear
    gemm64<64, false><<<NN / 32, 256, sm64>>>(x, W1, nullptr, p_hw);
    // 4. GCN1 aggregate (edges) + self-loop/bias/relu
    scatter64_kernel<<<EE / 8, 256>>>(ei, ea);
    post1_kernel<<<(NN * HIDD) / 256, 256>>>(b1);
    // 5. QKV projection
    gemm64<192, true><<<NN / 32, 256, sm192>>>(p_h, Win, b_in, p_qkv);
    // 6. attention
    attn_kernel<<<dim3(NN / 128, NHEADS), 128>>>();
    // 7. out projection
    gemm64<64, true><<<NN / 32, 256, sm64>>>(p_o, Wout, b_out, p_ow);
    // 8. GCN2 linear
    gemm64<86, false><<<NN / 32, 256, sm86>>>(p_ow, W2, nullptr, p_h2w);
    // 9. GCN2 aggregate + pool
    scatter86_kernel<<<EE / 8, 256>>>(ei, ea);
    cnt_kernel<<<NN / 256, 256>>>(batch);
    final_node_kernel<<<(NN * OUTD + 255) / 256, 256>>>(batch, b2);
    out_kernel<<<(BB * OUTD + 255) / 256, 256>>>(out);
}

// round 2
// speedup vs baseline: 3.4650x; 3.4650x over previous
#include <cuda_runtime.h>
#include <math.h>

#define NN 4096
#define EE 131072
#define FF 64
#define HIDD 64
#define OUTD 86
#define BB 16
#define NHEADS 4
#define DH 16

typedef unsigned long long ull;

// ------------------------- f32x2 packed helpers ----------------------------
__device__ __forceinline__ ull pk2(float lo, float hi) {
    ull r; asm("mov.b64 %0,{%1,%2};" : "=l"(r) : "f"(lo), "f"(hi)); return r;
}
__device__ __forceinline__ void upk2(ull v, float& lo, float& hi) {
    asm("mov.b64 {%0,%1},%2;" : "=f"(lo), "=f"(hi) : "l"(v));
}
__device__ __forceinline__ ull fma2(ull a, ull b, ull c) {
    ull d; asm("fma.rn.f32x2 %0,%1,%2,%3;" : "=l"(d) : "l"(a), "l"(b), "l"(c)); return d;
}
__device__ __forceinline__ ull mul2(ull a, ull b) {
    ull d; asm("mul.rn.f32x2 %0,%1,%2;" : "=l"(d) : "l"(a), "l"(b)); return d;
}

// ------------------------- scratch (device globals; no allocs) -------------
__device__ float g_deg[NN];
__device__ float g_dis[NN];
__device__ float g_hw[NN * HIDD];     // x @ W1^T
__device__ float g_agg1[NN * HIDD];   // scatter target GCN1
__device__ float g_h[NN * HIDD];      // relu(agg + selfloop + b1)
__device__ float g_qkv[NN * 3 * HIDD];
__device__ float g_o[NN * HIDD];      // attention output (pre out-proj)
__device__ float g_ow[NN * HIDD];     // o @ Wout^T + b_out
__device__ float g_h2w[NN * OUTD];    // ow @ W2^T
__device__ float g_agg2[NN * OUTD];   // scatter target GCN2
__device__ float g_pool[BB * OUTD];
__device__ float g_cnt[BB];

// ------------------------- init / degree / norm ----------------------------
__global__ void init_kernel() {
    int idx = blockIdx.x * blockDim.x + threadIdx.x;
    if (idx < NN * HIDD) g_agg1[idx] = 0.0f;
    if (idx < NN * OUTD) g_agg2[idx] = 0.0f;
    if (idx < BB * OUTD) g_pool[idx] = 0.0f;
    if (idx < BB) g_cnt[idx] = 0.0f;
    if (idx < NN) g_deg[idx] = 1.0f;   // self-loop weight 1
}

__global__ void deg_kernel(const int* __restrict__ ei, const float* __restrict__ ea) {
    int e = blockIdx.x * blockDim.x + threadIdx.x;
    if (e < EE) {
        int d = ei[EE + e];
        atomicAdd(&g_deg[d], ea[e]);
    }
}

__global__ void dis_kernel() {
    int i = blockIdx.x * blockDim.x + threadIdx.x;
    if (i < NN) g_dis[i] = rsqrtf(g_deg[i]);   // deg >= 1 always (self loops)
}

// ------------------------- GEMM v2: out = in @ W^T (+bias) -----------------
// in: [NN, 64], W: [KOUT, 64] row-major, out: [NN, KOUT]
// block: 128 threads (32x4), 16 rows/block, grid NN/16 = 256
template <int KOUT, bool BIAS>
__global__ void gemm64(const float* __restrict__ in, const float* __restrict__ W,
                       const float* __restrict__ bias, float* __restrict__ out) {
    constexpr int KP  = ((KOUT + 31) / 32) * 32;
    constexpr int KPP = KP + 1;
    constexpr int CT  = KP / 32;
    constexpr int RT  = 4;
    constexpr int ROWS = 16;
    extern __shared__ float sm[];
    float* Wsh = sm;                 // [64][KPP]  (k-major)
    float* xsh = sm + 64 * KPP;      // [ROWS][68]
    int tid = threadIdx.x;           // 128 threads

    for (int idx = tid; idx < 64 * KP; idx += 128) {
        int k = idx & 63;
        int c = idx >> 6;
        float w = (c < KOUT) ? W[c * 64 + k] : 0.0f;
        Wsh[k * KPP + c] = w;
    }
    int row0 = blockIdx.x * ROWS;
    for (int idx = tid; idx < ROWS * 64; idx += 128) {
        int r = idx >> 6, k = idx & 63;
        xsh[r * 68 + k] = in[(row0 + r) * 64 + k];
    }
    __syncthreads();

    int tx = tid & 31, ty = tid >> 5;   // ty 0..3
    float acc[RT][CT];
#pragma unroll
    for (int i = 0; i < RT; i++)
#pragma unroll
        for (int j = 0; j < CT; j++) acc[i][j] = 0.0f;

#pragma unroll
    for (int k4 = 0; k4 < 16; k4++) {
        float xs[RT][4];
#pragma unroll
        for (int i = 0; i < RT; i++)
            *(float4*)xs[i] = *(const float4*)&xsh[(ty * RT + i) * 68 + k4 * 4];
#pragma unroll
        for (int kk = 0; kk < 4; kk++) {
            float wv[CT];
#pragma unroll
            for (int j = 0; j < CT; j++) wv[j] = Wsh[(k4 * 4 + kk) * KPP + tx + j * 32];
#pragma unroll
            for (int i = 0; i < RT; i++)
#pragma unroll
                for (int j = 0; j < CT; j++)
                    acc[i][j] = fmaf(xs[i][kk], wv[j], acc[i][j]);
        }
    }
#pragma unroll
    for (int i = 0; i < RT; i++) {
        int r = row0 + ty * RT + i;
#pragma unroll
        for (int j = 0; j < CT; j++) {
            int c = tx + j * 32;
            if (c < KOUT) {
                float v = acc[i][j];
                if (BIAS) v += bias[c];
                out[r * KOUT + c] = v;
            }
        }
    }
}

// ------------------------- GCN scatter (warp per edge) ---------------------
__global__ void scatter64_kernel(const int* __restrict__ ei, const float* __restrict__ ea) {
    int w = (blockIdx.x * blockDim.x + threadIdx.x) >> 5;
    int lane = threadIdx.x & 31;
    if (w >= EE) return;
    int s = ei[w];
    int d = ei[EE + w];
    float coef = g_dis[s] * ea[w] * g_dis[d];
    float v0 = g_hw[s * 64 + lane];
    float v1 = g_hw[s * 64 + 32 + lane];
    atomicAdd(&g_agg1[d * 64 + lane], coef * v0);
    atomicAdd(&g_agg1[d * 64 + 32 + lane], coef * v1);
}

__global__ void post1_kernel(const float* __restrict__ b1) {
    int idx = blockIdx.x * blockDim.x + threadIdx.x;
    if (idx >= NN * HIDD) return;
    int i = idx >> 6, f = idx & 63;
    float di = g_dis[i];
    float v = g_agg1[idx] + di * di * g_hw[idx] + b1[f];
    g_h[idx] = fmaxf(v, 0.0f);
}

// ------------------------- flash attention v2 ------------------------------
// warp handles 2 queries of one head; lanes split keys (pairs); f32x2 math.
// grid (256, 4), block 256 (8 warps -> 16 queries/block).
__global__ void __launch_bounds__(256) attn_kernel() {
    int head = blockIdx.y;
    int warp = threadIdx.x >> 5;
    int lane = threadIdx.x & 31;
    int qbase = blockIdx.x * 16 + warp * 2;

    // K pairs: Ksh[jp*34 + d*2 + (j&1)] = K[2jp + (j&1)][d]
    // V pairs: Vsh[jp*34 + (j&1)*16 + d] = V[2jp + (j&1)][d]
    __shared__ float Ksh[64 * 34];
    __shared__ float Vsh[64 * 34];

    const float SC = 0.25f * 1.44269504088896f;   // 1/sqrt(dh) * log2(e)
    ull qd[2][16];
#pragma unroll
    for (int qq = 0; qq < 2; qq++) {
        const float* qp = g_qkv + (qbase + qq) * 192 + head * DH;
#pragma unroll
        for (int d = 0; d < 16; d++) {
            float v = qp[d] * SC;
            qd[qq][d] = pk2(v, v);
        }
    }

    ull acc[2][8];
    float m[2] = {-1e30f, -1e30f};
    float l[2] = {0.0f, 0.0f};
#pragma unroll
    for (int qq = 0; qq < 2; qq++)
#pragma unroll
        for (int dp = 0; dp < 8; dp++) acc[qq][dp] = 0ull;

    for (int t = 0; t < NN / 128; t++) {
        __syncthreads();
        for (int i = threadIdx.x; i < 2048; i += 256) {
            int j = i >> 4, d = i & 15;
            const float* base = g_qkv + (t * 128 + j) * 192 + head * DH;
            int jp = j >> 1, par = j & 1;
            Ksh[jp * 34 + d * 2 + par] = base[64 + d];
            Vsh[jp * 34 + par * 16 + d] = base[128 + d];
        }
        __syncthreads();

#pragma unroll
        for (int it = 0; it < 2; it++) {
            int jp = lane + it * 32;
            const float* kp = Ksh + jp * 34;
            ull s2[2] = {0ull, 0ull};
#pragma unroll
            for (int d = 0; d < 16; d++) {
                ull k2 = *(const ull*)(kp + d * 2);
                s2[0] = fma2(qd[0][d], k2, s2[0]);
                s2[1] = fma2(qd[1][d], k2, s2[1]);
            }
            const float* vp = Vsh + jp * 34;
            ull v0[8], v1[8];
#pragma unroll
            for (int dp = 0; dp < 8; dp++) {
                v0[dp] = *(const ull*)(vp + dp * 2);
                v1[dp] = *(const ull*)(vp + 16 + dp * 2);
            }
#pragma unroll
            for (int qq = 0; qq < 2; qq++) {
                float s0, s1;
                upk2(s2[qq], s0, s1);
                float mx = fmaxf(s0, s1);
                if (mx > m[qq]) {
                    float sc = exp2f(m[qq] - mx);
                    m[qq] = mx;
                    l[qq] *= sc;
                    ull sc2 = pk2(sc, sc);
#pragma unroll
                    for (int dp = 0; dp < 8; dp++) acc[qq][dp] = mul2(acc[qq][dp], sc2);
                }
                float p0 = exp2f(s0 - m[qq]);
                float p1 = exp2f(s1 - m[qq]);
                l[qq] += p0 + p1;
                ull pp0 = pk2(p0, p0), pp1 = pk2(p1, p1);
#pragma unroll
                for (int dp = 0; dp < 8; dp++)
                    acc[qq][dp] = fma2(pp1, v1[dp], fma2(pp0, v0[dp], acc[qq][dp]));
            }
        }
    }

    // cross-lane combine
#pragma unroll
    for (int qq = 0; qq < 2; qq++) {
        float a[16];
#pragma unroll
        for (int dp = 0; dp < 8; dp++) upk2(acc[qq][dp], a[dp * 2], a[dp * 2 + 1]);
        float mm = m[qq], ll = l[qq];
#pragma unroll
        for (int off = 16; off >= 1; off >>= 1) {
            float m2 = __shfl_xor_sync(0xFFFFFFFF, mm, off);
            float l2 = __shfl_xor_sync(0xFFFFFFFF, ll, off);
            float a2[16];
#pragma unroll
            for (int d = 0; d < 16; d++) a2[d] = __shfl_xor_sync(0xFFFFFFFF, a[d], off);
            float mn = fmaxf(mm, m2);
            float c1 = exp2f(mm - mn), c2 = exp2f(m2 - mn);
            ll = ll * c1 + l2 * c2;
#pragma unroll
            for (int d = 0; d < 16; d++) a[d] = a[d] * c1 + a2[d] * c2;
            mm = mn;
        }
        if (lane == 0) {
            float inv = 1.0f / ll;
            float* op = g_o + (qbase + qq) * 64 + head * DH;
#pragma unroll
            for (int d = 0; d < 16; d++) op[d] = a[d] * inv;
        }
    }
}

// ------------------------- GCN2 scatter (86 features) -----------------------
__global__ void scatter86_kernel(const int* __restrict__ ei, const float* __restrict__ ea) {
    int w = (blockIdx.x * blockDim.x + threadIdx.x) >> 5;
    int lane = threadIdx.x & 31;
    if (w >= EE) return;
    int s = ei[w];
    int d = ei[EE + w];
    float coef = g_dis[s] * ea[w] * g_dis[d];
    for (int f = lane; f < OUTD; f += 32) {
        atomicAdd(&g_agg2[d * OUTD + f], coef * g_h2w[s * OUTD + f]);
    }
}

__global__ void cnt_kernel(const int* __restrict__ batch) {
    int i = blockIdx.x * blockDim.x + threadIdx.x;
    if (i < NN) atomicAdd(&g_cnt[batch[i]], 1.0f);
}

__global__ void final_node_kernel(const int* __restrict__ batch, const float* __restrict__ b2) {
    int idx = blockIdx.x * blockDim.x + threadIdx.x;
    if (idx >= NN * OUTD) return;
    int i = idx / OUTD, f = idx - i * OUTD;
    float di = g_dis[i];
    float v = g_agg2[idx] + di * di * g_h2w[idx] + b2[f];
    atomicAdd(&g_pool[batch[i] * OUTD + f], v);
}

__global__ void out_kernel(float* __restrict__ out) {
    int idx = blockIdx.x * blockDim.x + threadIdx.x;
    if (idx >= BB * OUTD) return;
    int b = idx / OUTD;
    out[idx] = g_pool[idx] / fmaxf(g_cnt[b], 1.0f);
}

// ------------------------- launch ------------------------------------------
extern "C" void kernel_launch(void* const* d_in, const int* in_sizes, int n_in,
                              void* d_out, int out_size) {
    const float* x     = (const float*)d_in[0];
    const int*   ei    = (const int*)  d_in[1];
    const float* ea    = (const float*)d_in[2];
    const int*   batch = (const int*)  d_in[3];
    const float* W1    = (const float*)d_in[4];
    const float* b1    = (const float*)d_in[5];
    const float* Win   = (const float*)d_in[6];
    const float* b_in  = (const float*)d_in[7];
    const float* Wout  = (const float*)d_in[8];
    const float* b_out = (const float*)d_in[9];
    const float* W2    = (const float*)d_in[10];
    const float* b2    = (const float*)d_in[11];
    float* out = (float*)d_out;

    float *p_hw, *p_h, *p_qkv, *p_o, *p_ow, *p_h2w;
    cudaGetSymbolAddress((void**)&p_hw,  g_hw);
    cudaGetSymbolAddress((void**)&p_h,   g_h);
    cudaGetSymbolAddress((void**)&p_qkv, g_qkv);
    cudaGetSymbolAddress((void**)&p_o,   g_o);
    cudaGetSymbolAddress((void**)&p_ow,  g_ow);
    cudaGetSymbolAddress((void**)&p_h2w, g_h2w);

    // dynamic smem sizes for gemm64 variants: (64*(KP+1) + 16*68)*4
    const int sm64  = (64 * 65  + 16 * 68) * 4;   // 20992 B
    const int sm86  = (64 * 97  + 16 * 68) * 4;   // 29184 B
    const int sm192 = (64 * 193 + 16 * 68) * 4;   // 53760 B
    cudaFuncSetAttribute(gemm64<192, true>, cudaFuncAttributeMaxDynamicSharedMemorySize, sm192);

    // 1. zero / init
    init_kernel<<<(NN * OUTD + 255) / 256, 256>>>();
    // 2. degree accumulation + normalization factors
    deg_kernel<<<EE / 256, 256>>>(ei, ea);
    dis_kernel<<<NN / 256, 256>>>();
    // 3. GCN1 linear
    gemm64<64, false><<<NN / 16, 128, sm64>>>(x, W1, nullptr, p_hw);
    // 4. GCN1 aggregate (edges) + self-loop/bias/relu
    scatter64_kernel<<<EE / 8, 256>>>(ei, ea);
    post1_kernel<<<(NN * HIDD) / 256, 256>>>(b1);
    // 5. QKV projection
    gemm64<192, true><<<NN / 16, 128, sm192>>>(p_h, Win, b_in, p_qkv);
    // 6. attention
    attn_kernel<<<dim3(NN / 16, NHEADS), 256>>>();
    // 7. out projection
    gemm64<64, true><<<NN / 16, 128, sm64>>>(p_o, Wout, b_out, p_ow);
    // 8. GCN2 linear
    gemm64<86, false><<<NN / 16, 128, sm86>>>(p_ow, W2, nullptr, p_h2w);
    // 9. GCN2 aggregate + pool
    scatter86_kernel<<<EE / 8, 256>>>(ei, ea);
    cnt_kernel<<<NN / 256, 256>>>(batch);
    final_node_kernel<<<(NN * OUTD + 255) / 256, 256>>>(batch, b2);
    out_kernel<<<(BB * OUTD + 255) / 256, 256>>>(out);
}

// round 3
// speedup vs baseline: 4.2116x; 1.2155x over previous
#include <cuda_runtime.h>
#include <math.h>

#define NN 4096
#define EE 131072
#define HIDD 64
#define OUTD 86
#define OUTP 88          // padded stride for GCN2 feature dim
#define BB 16
#define NHEADS 4
#define DH 16
#define CHUNKS 8
#define CKEYS (NN / CHUNKS)   // 512 keys per chunk

typedef unsigned long long ull;

// ------------------------- f32x2 packed helpers ----------------------------
__device__ __forceinline__ ull pk2(float lo, float hi) {
    ull r; asm("mov.b64 %0,{%1,%2};" : "=l"(r) : "f"(lo), "f"(hi)); return r;
}
__device__ __forceinline__ void upk2(ull v, float& lo, float& hi) {
    asm("mov.b64 {%0,%1},%2;" : "=f"(lo), "=f"(hi) : "l"(v));
}
__device__ __forceinline__ ull fma2(ull a, ull b, ull c) {
    ull d; asm("fma.rn.f32x2 %0,%1,%2,%3;" : "=l"(d) : "l"(a), "l"(b), "l"(c)); return d;
}
__device__ __forceinline__ ull mul2(ull a, ull b) {
    ull d; asm("mul.rn.f32x2 %0,%1,%2;" : "=l"(d) : "l"(a), "l"(b)); return d;
}
__device__ __forceinline__ ull add2(ull a, ull b) {
    ull d; asm("add.rn.f32x2 %0,%1,%2;" : "=l"(d) : "l"(a), "l"(b)); return d;
}
__device__ __forceinline__ float ex2(float x) {
    float y; asm("ex2.approx.ftz.f32 %0,%1;" : "=f"(y) : "f"(x)); return y;
}

// ------------------------- scratch (device globals; no allocs) -------------
__device__ float g_deg[NN];
__device__ float g_dis[NN];
__device__ float g_hw[NN * HIDD];
__device__ float g_agg1[NN * HIDD];
__device__ float g_h[NN * HIDD];
__device__ float g_qkv[NN * 3 * HIDD];
__device__ float g_o[NN * HIDD];
__device__ float g_ow[NN * HIDD];
__device__ float g_h2w[NN * OUTP];     // padded; cols 86,87 stay 0
__device__ float g_agg2[NN * OUTP];
__device__ float g_pool[BB * OUTD];
__device__ float g_cnt[BB];
// attention split-K partials
__device__ float g_pm[NHEADS * CHUNKS * NN];
__device__ float g_pl[NHEADS * CHUNKS * NN];
__device__ float g_pacc[NHEADS * CHUNKS * NN * DH];

// ------------------------- init / degree / norm ----------------------------
__global__ void init_kernel() {
    int idx = blockIdx.x * blockDim.x + threadIdx.x;
    if (idx < NN * HIDD) g_agg1[idx] = 0.0f;
    if (idx < NN * OUTP) g_agg2[idx] = 0.0f;
    if (idx < BB * OUTD) g_pool[idx] = 0.0f;
    if (idx < BB) g_cnt[idx] = 0.0f;
    if (idx < NN) g_deg[idx] = 1.0f;   // self-loop weight 1
}

// degree atomics + batch counts in one launch
__global__ void accum_kernel(const int* __restrict__ ei, const float* __restrict__ ea,
                             const int* __restrict__ batch) {
    int e = blockIdx.x * blockDim.x + threadIdx.x;
    if (e < EE) atomicAdd(&g_deg[ei[EE + e]], ea[e]);
    if (e < NN) atomicAdd(&g_cnt[batch[e]], 1.0f);
}

__global__ void dis_kernel() {
    int i = blockIdx.x * blockDim.x + threadIdx.x;
    if (i < NN) g_dis[i] = rsqrtf(g_deg[i]);
}

// ------------------------- warp-per-2-rows GEMM ----------------------------
// in: [NN,64], W: [KOUT,64], out[r*OST + c]. block 256 (8 warps, 16 rows).
template <int KOUT, int OST, bool BIAS>
__global__ void __launch_bounds__(256) rowgemm(const float* __restrict__ in,
                                               const float* __restrict__ W,
                                               const float* __restrict__ bias,
                                               float* __restrict__ out) {
    constexpr int CT = (KOUT + 31) / 32;
    __shared__ __align__(16) float xsh[16][64];
    int lane = threadIdx.x & 31;
    int warp = threadIdx.x >> 5;
    int row0 = blockIdx.x * 16;
    {   // stage 16 rows (4KB): each thread one float4
        int r = threadIdx.x >> 4, c4 = threadIdx.x & 15;
        *(float4*)&xsh[r][c4 * 4] = *(const float4*)&in[(row0 + r) * 64 + c4 * 4];
    }
    __syncthreads();

    int r0 = warp * 2;
    float acc[2][CT];
#pragma unroll
    for (int i = 0; i < 2; i++)
#pragma unroll
        for (int j = 0; j < CT; j++) acc[i][j] = 0.0f;

#pragma unroll
    for (int k4 = 0; k4 < 16; k4++) {
        float4 xa = *(const float4*)&xsh[r0][k4 * 4];
        float4 xb = *(const float4*)&xsh[r0 + 1][k4 * 4];
#pragma unroll
        for (int j = 0; j < CT; j++) {
            int c = lane + j * 32;
            float4 w;
            if ((KOUT & 31) == 0 || c < KOUT)
                w = *(const float4*)&W[c * 64 + k4 * 4];
            else
                w = make_float4(0.f, 0.f, 0.f, 0.f);
            acc[0][j] = fmaf(xa.x, w.x, acc[0][j]); acc[0][j] = fmaf(xa.y, w.y, acc[0][j]);
            acc[0][j] = fmaf(xa.z, w.z, acc[0][j]); acc[0][j] = fmaf(xa.w, w.w, acc[0][j]);
            acc[1][j] = fmaf(xb.x, w.x, acc[1][j]); acc[1][j] = fmaf(xb.y, w.y, acc[1][j]);
            acc[1][j] = fmaf(xb.z, w.z, acc[1][j]); acc[1][j] = fmaf(xb.w, w.w, acc[1][j]);
        }
    }
#pragma unroll
    for (int i = 0; i < 2; i++) {
        int r = row0 + r0 + i;
#pragma unroll
        for (int j = 0; j < CT; j++) {
            int c = lane + j * 32;
            if ((KOUT & 31) == 0 || c < KOUT) {
                float v = acc[i][j];
                if (BIAS) v += bias[c];
                out[r * OST + c] = v;
            }
        }
    }
}

// ------------------------- GCN1 scatter: 16 lanes/edge, red.v4 -------------
__global__ void scatter64_kernel(const int* __restrict__ ei, const float* __restrict__ ea) {
    int gtid = blockIdx.x * blockDim.x + threadIdx.x;
    int e = gtid >> 4;
    if (e >= EE) return;
    int l16 = gtid & 15;
    int s = ei[e];
    int d = ei[EE + e];
    float coef = g_dis[s] * ea[e] * g_dis[d];
    float4 v = *(const float4*)&g_hw[s * 64 + l16 * 4];
    float* p = &g_agg1[d * 64 + l16 * 4];
    asm volatile("red.global.add.v4.f32 [%0], {%1,%2,%3,%4};"
                 :: "l"(p), "f"(coef * v.x), "f"(coef * v.y),
                    "f"(coef * v.z), "f"(coef * v.w) : "memory");
}

__global__ void post1_kernel(const float* __restrict__ b1) {
    int idx = blockIdx.x * blockDim.x + threadIdx.x;  // float4 units, NN*16
    if (idx >= NN * 16) return;
    int i = idx >> 4, c4 = idx & 15;
    float di = g_dis[i];
    float d2 = di * di;
    float4 a = *(const float4*)&g_agg1[idx * 4];
    float4 hw = *(const float4*)&g_hw[idx * 4];
    float4 bb = *(const float4*)&b1[c4 * 4];
    float4 r;
    r.x = fmaxf(a.x + d2 * hw.x + bb.x, 0.f);
    r.y = fmaxf(a.y + d2 * hw.y + bb.y, 0.f);
    r.z = fmaxf(a.z + d2 * hw.z + bb.z, 0.f);
    r.w = fmaxf(a.w + d2 * hw.w + bb.w, 0.f);
    *(float4*)&g_h[idx * 4] = r;
}

// ------------------------- attention: query-per-lane, split-K --------------
// grid (32, NHEADS, CHUNKS), block 128. Each warp: 32 queries, all keys of its
// chunk via smem broadcast. Partial (m,l,acc) per chunk.
__global__ void __launch_bounds__(128) attn_kernel() {
    int h = blockIdx.y, chunk = blockIdx.z;
    int lane = threadIdx.x & 31;
    int warp = threadIdx.x >> 5;
    int q = blockIdx.x * 128 + warp * 32 + lane;

    __shared__ __align__(16) float Ksh[128 * 16];
    __shared__ __align__(16) float Vsh[128 * 16];

    const float SC = 0.25f * 1.44269504088896f;  // 1/sqrt(dh)*log2(e)
    const float* qp = g_qkv + q * 192 + h * DH;
    ull q2[8];
#pragma unroll
    for (int dp = 0; dp < 8; dp++)
        q2[dp] = pk2(qp[2 * dp] * SC, qp[2 * dp + 1] * SC);

    float m = -1e30f, l = 0.0f;
    ull acc[8];
#pragma unroll
    for (int dp = 0; dp < 8; dp++) acc[dp] = 0ull;

    for (int t = 0; t < CKEYS / 128; t++) {
        int key0 = chunk * CKEYS + t * 128;
        __syncthreads();
#pragma unroll
        for (int i = threadIdx.x; i < 512; i += 128) {
            int j = i >> 2, c4 = i & 3;
            const float* kb = g_qkv + (key0 + j) * 192 + 64 + h * DH + c4 * 4;
            *(float4*)&Ksh[j * 16 + c4 * 4] = *(const float4*)kb;
            *(float4*)&Vsh[j * 16 + c4 * 4] = *(const float4*)(kb + 64);
        }
        __syncthreads();

#pragma unroll 4
        for (int j = 0; j < 128; j++) {
            const float* kr = Ksh + j * 16;
            ulonglong2 ka = *(const ulonglong2*)(kr);
            ulonglong2 kb = *(const ulonglong2*)(kr + 4);
            ulonglong2 kc = *(const ulonglong2*)(kr + 8);
            ulonglong2 kd = *(const ulonglong2*)(kr + 12);
            ull sa = fma2(q2[1], ka.y, mul2(q2[0], ka.x));
            ull sb = fma2(q2[3], kb.y, mul2(q2[2], kb.x));
            ull sc2 = fma2(q2[5], kc.y, mul2(q2[4], kc.x));
            ull sd = fma2(q2[7], kd.y, mul2(q2[6], kd.x));
            ull st = add2(add2(sa, sb), add2(sc2, sd));
            float lo, hi;
            upk2(st, lo, hi);
            float s = lo + hi;
            if (s > m) {               // taken once (first key), then never: margin 32
                float r = ex2(m - s - 32.0f);
                m = s + 32.0f;
                l *= r;
                ull r2 = pk2(r, r);
#pragma unroll
                for (int dp = 0; dp < 8; dp++) acc[dp] = mul2(acc[dp], r2);
            }
            float p = ex2(s - m);
            l += p;
            ull pp = pk2(p, p);
            const float* vr = Vsh + j * 16;
            ulonglong2 va = *(const ulonglong2*)(vr);
            ulonglong2 vb = *(const ulonglong2*)(vr + 4);
            ulonglong2 vc = *(const ulonglong2*)(vr + 8);
            ulonglong2 vd = *(const ulonglong2*)(vr + 12);
            acc[0] = fma2(pp, va.x, acc[0]); acc[1] = fma2(pp, va.y, acc[1]);
            acc[2] = fma2(pp, vb.x, acc[2]); acc[3] = fma2(pp, vb.y, acc[3]);
            acc[4] = fma2(pp, vc.x, acc[4]); acc[5] = fma2(pp, vc.y, acc[5]);
            acc[6] = fma2(pp, vd.x, acc[6]); acc[7] = fma2(pp, vd.y, acc[7]);
        }
    }

    int idx = (h * CHUNKS + chunk) * NN + q;
    g_pm[idx] = m;
    g_pl[idx] = l;
    ulonglong2* row = (ulonglong2*)&g_pacc[(size_t)idx * DH];
#pragma unroll
    for (int dp4 = 0; dp4 < 4; dp4++) {
        ulonglong2 w2; w2.x = acc[dp4 * 2]; w2.y = acc[dp4 * 2 + 1];
        row[dp4] = w2;
    }
}

__global__ void attn_combine() {
    int t = blockIdx.x * blockDim.x + threadIdx.x;  // 16384
    if (t >= NHEADS * NN) return;
    int h = t >> 12, q = t & (NN - 1);
    float m = -1e30f;
#pragma unroll
    for (int c = 0; c < CHUNKS; c++)
        m = fmaxf(m, g_pm[(h * CHUNKS + c) * NN + q]);
    float l = 0.0f;
    float o[16];
#pragma unroll
    for (int d = 0; d < 16; d++) o[d] = 0.0f;
#pragma unroll
    for (int c = 0; c < CHUNKS; c++) {
        int idx = (h * CHUNKS + c) * NN + q;
        float w = ex2(g_pm[idx] - m);
        l += g_pl[idx] * w;
        const float4* row = (const float4*)&g_pacc[(size_t)idx * DH];
#pragma unroll
        for (int d4 = 0; d4 < 4; d4++) {
            float4 a = row[d4];
            o[d4 * 4 + 0] += a.x * w; o[d4 * 4 + 1] += a.y * w;
            o[d4 * 4 + 2] += a.z * w; o[d4 * 4 + 3] += a.w * w;
        }
    }
    float inv = 1.0f / l;
    float* op = g_o + q * 64 + h * DH;
#pragma unroll
    for (int d = 0; d < 16; d++) op[d] = o[d] * inv;
}

// ------------------------- GCN2 scatter: warp/edge, 22 v4 lanes ------------
__global__ void scatter88_kernel(const int* __restrict__ ei, const float* __restrict__ ea) {
    int gtid = blockIdx.x * blockDim.x + threadIdx.x;
    int e = gtid >> 5;
    if (e >= EE) return;
    int lane = gtid & 31;
    if (lane >= 22) return;
    int s = ei[e];
    int d = ei[EE + e];
    float coef = g_dis[s] * ea[e] * g_dis[d];
    float4 v = *(const float4*)&g_h2w[s * OUTP + lane * 4];
    float* p = &g_agg2[d * OUTP + lane * 4];
    asm volatile("red.global.add.v4.f32 [%0], {%1,%2,%3,%4};"
                 :: "l"(p), "f"(coef * v.x), "f"(coef * v.y),
                    "f"(coef * v.z), "f"(coef * v.w) : "memory");
}

__global__ void final_node_kernel(const int* __restrict__ batch, const float* __restrict__ b2) {
    int idx = blockIdx.x * blockDim.x + threadIdx.x;
    if (idx >= NN * OUTP) return;
    int i = idx / OUTP, f = idx - i * OUTP;
    if (f >= OUTD) return;
    float di = g_dis[i];
    float v = g_agg2[idx] + di * di * g_h2w[idx] + b2[f];
    atomicAdd(&g_pool[batch[i] * OUTD + f], v);
}

__global__ void out_kernel(float* __restrict__ out) {
    int idx = blockIdx.x * blockDim.x + threadIdx.x;
    if (idx >= BB * OUTD) return;
    int b = idx / OUTD;
    out[idx] = g_pool[idx] / fmaxf(g_cnt[b], 1.0f);
}

// ------------------------- launch ------------------------------------------
extern "C" void kernel_launch(void* const* d_in, const int* in_sizes, int n_in,
                              void* d_out, int out_size) {
    const float* x     = (const float*)d_in[0];
    const int*   ei    = (const int*)  d_in[1];
    const float* ea    = (const float*)d_in[2];
    const int*   batch = (const int*)  d_in[3];
    const float* W1    = (const float*)d_in[4];
    const float* b1    = (const float*)d_in[5];
    const float* Win   = (const float*)d_in[6];
    const float* b_in  = (const float*)d_in[7];
    const float* Wout  = (const float*)d_in[8];
    const float* b_out = (const float*)d_in[9];
    const float* W2    = (const float*)d_in[10];
    const float* b2    = (const float*)d_in[11];
    float* out = (float*)d_out;

    float *p_hw, *p_h, *p_qkv, *p_o, *p_ow, *p_h2w;
    cudaGetSymbolAddress((void**)&p_hw,  g_hw);
    cudaGetSymbolAddress((void**)&p_h,   g_h);
    cudaGetSymbolAddress((void**)&p_qkv, g_qkv);
    cudaGetSymbolAddress((void**)&p_o,   g_o);
    cudaGetSymbolAddress((void**)&p_ow,  g_ow);
    cudaGetSymbolAddress((void**)&p_h2w, g_h2w);

    // 1. zero accumulators
    init_kernel<<<(NN * OUTP + 255) / 256, 256>>>();
    // 2. degree + batch counts
    accum_kernel<<<EE / 256, 256>>>(ei, ea, batch);
    dis_kernel<<<NN / 256, 256>>>();
    // 3. GCN1 linear
    rowgemm<64, 64, false><<<NN / 16, 256>>>(x, W1, nullptr, p_hw);
    // 4. GCN1 aggregate + post
    scatter64_kernel<<<EE * 16 / 256, 256>>>(ei, ea);
    post1_kernel<<<NN * 16 / 256, 256>>>(b1);
    // 5. QKV projection
    rowgemm<192, 192, true><<<NN / 16, 256>>>(p_h, Win, b_in, p_qkv);
    // 6. attention (split-K partials + combine)
    attn_kernel<<<dim3(NN / 128, NHEADS, CHUNKS), 128>>>();
    attn_combine<<<(NHEADS * NN) / 256, 256>>>();
    // 7. out projection
    rowgemm<64, 64, true><<<NN / 16, 256>>>(p_o, Wout, b_out, p_ow);
    // 8. GCN2 linear (padded stride 88)
    rowgemm<86, 88, false><<<NN / 16, 256>>>(p_ow, W2, nullptr, p_h2w);
    // 9. GCN2 aggregate + pool
    scatter88_kernel<<<EE * 32 / 256, 256>>>(ei, ea);
    final_node_kernel<<<(NN * OUTP + 255) / 256, 256>>>(batch, b2);
    out_kernel<<<(BB * OUTD + 255) / 256, 256>>>(out);
}